// round 14
// baseline (speedup 1.0000x reference)
#include <cuda_runtime.h>
#include <cuda_bf16.h>
#include <cstdint>
#include <math.h>

#define BDIM 4
#define TDIM 2048
#define CDIM 1024
#define HDIM 2048

#define BM 128
#define BN 128
#define BK 16
#define SPADH 24                 // bf16 per smem row (48B rows: LDSM conflict-free)
#define TILE_E (BM * SPADH)      // 3072 bf16 per tile buffer
#define TILE_B (TILE_E * 2)      // 6144 bytes
#define NSTAGE 3
#define SMEM_BYTES (NSTAGE * 4 * TILE_B)   // 73728 -> 2 CTAs/SM

// ---- global scratch planes (allocation-free rule) ----
#define NXC ((size_t)BDIM * TDIM * CDIM)
#define NWH ((size_t)HDIM * CDIM)
#define NTH ((size_t)BDIM * TDIM * HDIM)
#define NTT ((size_t)BDIM * TDIM * TDIM)
__device__ __nv_bfloat16 g_xh[NXC], g_xl[NXC];
__device__ __nv_bfloat16 g_wh[3][NWH], g_wl[3][NWH];
__device__ __nv_bfloat16 g_qkvh[3 * NTH], g_qkvl[3 * NTH];   // q,k,v planes stacked
__device__ __nv_bfloat16 g_vth[NTH], g_vtl[NTH];
__device__ float g_s[NTT];
__device__ __nv_bfloat16 g_ph[NTT], g_pl[NTT];

// m16n8k16 bf16 MMA (sm_80+ baseline PTX)
__device__ __forceinline__ void mma_bf16(float* c, const uint32_t* a, const uint32_t* b) {
    asm volatile(
        "mma.sync.aligned.m16n8k16.row.col.f32.bf16.bf16.f32 "
        "{%0,%1,%2,%3}, {%4,%5,%6,%7}, {%8,%9}, {%0,%1,%2,%3};"
        : "+f"(c[0]), "+f"(c[1]), "+f"(c[2]), "+f"(c[3])
        : "r"(a[0]), "r"(a[1]), "r"(a[2]), "r"(a[3]), "r"(b[0]), "r"(b[1]));
}

__device__ __forceinline__ void ldsm_x4(uint32_t* r, uint32_t addr) {
    asm volatile("ldmatrix.sync.aligned.m8n8.x4.shared.b16 {%0,%1,%2,%3}, [%4];"
                 : "=r"(r[0]), "=r"(r[1]), "=r"(r[2]), "=r"(r[3]) : "r"(addr));
}

#define CP_COMMIT() asm volatile("cp.async.commit_group;" ::: "memory")
#define CP_WAIT0()  asm volatile("cp.async.wait_group 0;" ::: "memory")
#define CP_WAIT1()  asm volatile("cp.async.wait_group 1;" ::: "memory")

// ---------------- 3xBF16 NT GEMM, 3-stage cp.async ring, LDSM frags ----------------
// C[m,n] = sum_k A[m*K+k]*B[n*K+k], A/B given as hi/lo bf16 planes (K-major).
// split=0: write f32 to Cf.  split=1: write hi/lo bf16 planes Ch/Cl.
__global__ __launch_bounds__(256, 2) void mma_nt(
    const __nv_bfloat16* __restrict__ Ah, const __nv_bfloat16* __restrict__ Al,
    const __nv_bfloat16* __restrict__ Bh, const __nv_bfloat16* __restrict__ Bl,
    float* __restrict__ Cf, __nv_bfloat16* __restrict__ Ch, __nv_bfloat16* __restrict__ Cl,
    int K, int ldc, long sA, long sB, long sC, int causal, int clampk, int split)
{
    const int m0 = blockIdx.y * BM;
    const int n0 = blockIdx.x * BN;
    if (causal && n0 > m0) return;

    const int b = blockIdx.z;
    Ah += (long)b * sA;  Al += (long)b * sA;
    Bh += (long)b * sB;  Bl += (long)b * sB;

    extern __shared__ __nv_bfloat16 sm[];
    const uint32_t smb = (uint32_t)__cvta_generic_to_shared(sm);

    const int tid  = threadIdx.x;
    const int wid  = tid >> 5;
    const int lane = tid & 31;
    const int g  = lane >> 2;
    const int tg = lane & 3;
    const int wm = (wid >> 2) * 64;
    const int wn = (wid & 3) * 32;

    // LDSM per-thread addresses (bytes). 48B rows: 12r mod 32 covers all bank groups.
    const uint32_t a_base = smb + (uint32_t)(((wm + (lane & 15)) * SPADH + ((lane >> 4) << 3)) * 2);
    const uint32_t b_base = smb + (uint32_t)(((wn + ((lane >> 4) << 3) + (lane & 7)) * SPADH
                                              + (((lane >> 3) & 1) << 3)) * 2);

    const int kEnd = clampk ? (m0 + BM) : K;
    const int nstages = kEnd / BK;

    // cp.async: one 16B chunk per plane per thread (128 rows x 2 chunks = 256)
    const int rc = tid >> 1, cc = tid & 1;

    const __nv_bfloat16* planes[4] = {Ah, Al, Bh, Bl};
    const int rbase[4] = {m0, m0, n0, n0};

    auto load_stage = [&](int buf, int k0) {
        #pragma unroll
        for (int p = 0; p < 4; p++) {
            uint32_t dst = smb + (uint32_t)(((buf * 4 + p) * TILE_E + rc * SPADH + cc * 8) * 2);
            const void* src = planes[p] + (long)(rbase[p] + rc) * K + k0 + cc * 8;
            asm volatile("cp.async.cg.shared.global [%0], [%1], 16;" :: "r"(dst), "l"(src));
        }
        CP_COMMIT();
    };

    float acc[4][4][4] = {};

    load_stage(0, 0);
    load_stage(1, BK);

    for (int s = 0; s < nstages; s++) {
        if (s + 1 < nstages) CP_WAIT1(); else CP_WAIT0();
        __syncthreads();                       // stage s visible; compute(s-1) done by all
        if (s + 2 < nstages) load_stage((s + 2) % NSTAGE, (s + 2) * BK);

        const int buf = s % NSTAGE;
        const uint32_t tAh = (uint32_t)((buf * 4 + 0) * TILE_B);
        const uint32_t tAl = (uint32_t)((buf * 4 + 1) * TILE_B);
        const uint32_t tBh = (uint32_t)((buf * 4 + 2) * TILE_B);
        const uint32_t tBl = (uint32_t)((buf * 4 + 3) * TILE_B);

        uint32_t af[4][4], bh[2][4];

        // Phase 1: ah * bh
        #pragma unroll
        for (int mt = 0; mt < 4; mt++)
            ldsm_x4(af[mt], a_base + tAh + (uint32_t)(mt * 16 * SPADH * 2));
        #pragma unroll
        for (int p = 0; p < 2; p++)
            ldsm_x4(bh[p], b_base + tBh + (uint32_t)(p * 16 * SPADH * 2));
        #pragma unroll
        for (int mt = 0; mt < 4; mt++)
            #pragma unroll
            for (int nt = 0; nt < 4; nt++)
                mma_bf16(acc[mt][nt], af[mt], &bh[nt >> 1][(nt & 1) * 2]);

        // Phase 2: ah * bl
        uint32_t bl[2][4];
        #pragma unroll
        for (int p = 0; p < 2; p++)
            ldsm_x4(bl[p], b_base + tBl + (uint32_t)(p * 16 * SPADH * 2));
        #pragma unroll
        for (int mt = 0; mt < 4; mt++)
            #pragma unroll
            for (int nt = 0; nt < 4; nt++)
                mma_bf16(acc[mt][nt], af[mt], &bl[nt >> 1][(nt & 1) * 2]);

        // Phase 3: al * bh (reuse af regs for Al)
        #pragma unroll
        for (int mt = 0; mt < 4; mt++)
            ldsm_x4(af[mt], a_base + tAl + (uint32_t)(mt * 16 * SPADH * 2));
        #pragma unroll
        for (int mt = 0; mt < 4; mt++)
            #pragma unroll
            for (int nt = 0; nt < 4; nt++)
                mma_bf16(acc[mt][nt], af[mt], &bh[nt >> 1][(nt & 1) * 2]);
    }

    // ---- epilogue ----
    if (split) {
        Ch += (long)blockIdx.z * sC;  Cl += (long)blockIdx.z * sC;
        #pragma unroll
        for (int mt = 0; mt < 4; mt++) {
            #pragma unroll
            for (int nt = 0; nt < 4; nt++) {
                const int row = m0 + wm + mt * 16 + g;
                const int col = n0 + wn + nt * 8 + tg * 2;
                #pragma unroll
                for (int h = 0; h < 2; h++) {
                    float2 v = {acc[mt][nt][2 * h], acc[mt][nt][2 * h + 1]};
                    __nv_bfloat162 hp = __float22bfloat162_rn(v);
                    __nv_bfloat162 lp = __float22bfloat162_rn(make_float2(
                        v.x - __bfloat162float(hp.x), v.y - __bfloat162float(hp.y)));
                    long off = (long)(row + 8 * h) * ldc + col;
                    *(__nv_bfloat162*)&Ch[off] = hp;
                    *(__nv_bfloat162*)&Cl[off] = lp;
                }
            }
        }
    } else {
        Cf += (long)blockIdx.z * sC;
        #pragma unroll
        for (int mt = 0; mt < 4; mt++) {
            #pragma unroll
            for (int nt = 0; nt < 4; nt++) {
                const int row = m0 + wm + mt * 16 + g;
                const int col = n0 + wn + nt * 8 + tg * 2;
                float2 lo = {acc[mt][nt][0], acc[mt][nt][1]};
                float2 hi = {acc[mt][nt][2], acc[mt][nt][3]};
                *(float2*)&Cf[(long)row * ldc + col] = lo;
                *(float2*)&Cf[(long)(row + 8) * ldc + col] = hi;
            }
        }
    }
}

// ---------------- f32 -> hi/lo bf16 planes ----------------
__global__ __launch_bounds__(256) void split_f32(
    const float* __restrict__ src, __nv_bfloat16* __restrict__ h,
    __nv_bfloat16* __restrict__ l, long n4)
{
    long i = ((long)blockIdx.x * 256 + threadIdx.x);
    if (i >= n4) return;
    float4 v = *(const float4*)(src + i * 4);
    __nv_bfloat162 h01 = __float22bfloat162_rn(make_float2(v.x, v.y));
    __nv_bfloat162 h23 = __float22bfloat162_rn(make_float2(v.z, v.w));
    __nv_bfloat162 l01 = __float22bfloat162_rn(make_float2(
        v.x - __bfloat162float(h01.x), v.y - __bfloat162float(h01.y)));
    __nv_bfloat162 l23 = __float22bfloat162_rn(make_float2(
        v.z - __bfloat162float(h23.x), v.w - __bfloat162float(h23.y)));
    *(__nv_bfloat162*)&h[i * 4]     = h01;
    *(__nv_bfloat162*)&h[i * 4 + 2] = h23;
    *(__nv_bfloat162*)&l[i * 4]     = l01;
    *(__nv_bfloat162*)&l[i * 4 + 2] = l23;
}

// ---------------- causal softmax -> hi/lo bf16 P planes ----------------
__global__ __launch_bounds__(256) void softmax_causal(
    const float* __restrict__ S, __nv_bfloat16* __restrict__ Ph,
    __nv_bfloat16* __restrict__ Pl, float scale)
{
    const int t = blockIdx.x;
    const int b = blockIdx.y;
    const long ro = ((long)b * TDIM + t) * TDIM;
    const float* row = S + ro;
    const int n = t + 1;
    const int nend = ((t >> 7) + 1) << 7;
    const int tid = threadIdx.x;

    __shared__ float red[256];

    float mx = -INFINITY;
    for (int i = tid; i < n; i += 256) mx = fmaxf(mx, row[i] * scale);
    red[tid] = mx;
    __syncthreads();
    for (int s = 128; s > 0; s >>= 1) {
        if (tid < s) red[tid] = fmaxf(red[tid], red[tid + s]);
        __syncthreads();
    }
    mx = red[0];
    __syncthreads();

    float sum = 0.f;
    for (int i = tid; i < n; i += 256) sum += __expf(row[i] * scale - mx);
    red[tid] = sum;
    __syncthreads();
    for (int s = 128; s > 0; s >>= 1) {
        if (tid < s) red[tid] += red[tid + s];
        __syncthreads();
    }
    const float inv = 1.0f / red[0];

    for (int i = tid; i < n; i += 256) {
        float p = __expf(row[i] * scale - mx) * inv;
        __nv_bfloat16 hp = __float2bfloat16_rn(p);
        Ph[ro + i] = hp;
        Pl[ro + i] = __float2bfloat16_rn(p - __bfloat162float(hp));
    }
    const __nv_bfloat16 z = __float2bfloat16_rn(0.f);
    for (int i = n + tid; i < nend; i += 256) { Ph[ro + i] = z; Pl[ro + i] = z; }
}

// ---------------- transpose both V planes: vt[b][h][t] = v[b][t][h] ----------------
__global__ __launch_bounds__(256) void transpose_bth(
    const __nv_bfloat16* __restrict__ Vh, const __nv_bfloat16* __restrict__ Vl,
    __nv_bfloat16* __restrict__ VTh, __nv_bfloat16* __restrict__ VTl)
{
    __shared__ __nv_bfloat16 th[32][33], tl[32][33];
    const int b = blockIdx.z;
    const int t0 = blockIdx.x * 32;
    const int h0 = blockIdx.y * 32;
    const int tx = threadIdx.x, ty = threadIdx.y;   // 32 x 8

    const long vo = (long)b * TDIM * HDIM;

    #pragma unroll
    for (int i = 0; i < 4; i++) {
        long src = vo + (long)(t0 + ty + 8 * i) * HDIM + h0 + tx;
        th[ty + 8 * i][tx] = Vh[src];
        tl[ty + 8 * i][tx] = Vl[src];
    }
    __syncthreads();
    #pragma unroll
    for (int i = 0; i < 4; i++) {
        long dst = vo + (long)(h0 + ty + 8 * i) * TDIM + t0 + tx;
        VTh[dst] = th[tx][ty + 8 * i];
        VTl[dst] = tl[tx][ty + 8 * i];
    }
}

// ---------------- driver ----------------
extern "C" void kernel_launch(void* const* d_in, const int* in_sizes, int n_in,
                              void* d_out, int out_size)
{
    const float* x  = (const float*)d_in[0];
    const float* Wk = (const float*)d_in[1];
    const float* Wq = (const float*)d_in[2];
    const float* Wv = (const float*)d_in[3];
    float* out = (float*)d_out;

    __nv_bfloat16 *xh, *xl, *wh0, *wl0, *qkvh, *qkvl, *vth, *vtl, *ph, *pl;
    float* s;
    cudaGetSymbolAddress((void**)&xh,   g_xh);    cudaGetSymbolAddress((void**)&xl,   g_xl);
    cudaGetSymbolAddress((void**)&wh0,  g_wh);    cudaGetSymbolAddress((void**)&wl0,  g_wl);
    cudaGetSymbolAddress((void**)&qkvh, g_qkvh);  cudaGetSymbolAddress((void**)&qkvl, g_qkvl);
    cudaGetSymbolAddress((void**)&vth,  g_vth);   cudaGetSymbolAddress((void**)&vtl,  g_vtl);
    cudaGetSymbolAddress((void**)&ph,   g_ph);    cudaGetSymbolAddress((void**)&pl,   g_pl);
    cudaGetSymbolAddress((void**)&s,    g_s);

    cudaFuncSetAttribute(mma_nt, cudaFuncAttributeMaxDynamicSharedMemorySize, SMEM_BYTES);

    const int M = BDIM * TDIM;   // 8192

    // split inputs into hi/lo bf16 planes (weight order: q, k, v)
    {
        long nx4 = NXC / 4, nw4 = NWH / 4;
        split_f32<<<(unsigned)((nx4 + 255) / 256), 256>>>(x, xh, xl, nx4);
        split_f32<<<(unsigned)((nw4 + 255) / 256), 256>>>(Wq, wh0 + 0 * NWH, wl0 + 0 * NWH, nw4);
        split_f32<<<(unsigned)((nw4 + 255) / 256), 256>>>(Wk, wh0 + 1 * NWH, wl0 + 1 * NWH, nw4);
        split_f32<<<(unsigned)((nw4 + 255) / 256), 256>>>(Wv, wh0 + 2 * NWH, wl0 + 2 * NWH, nw4);
    }

    // All three projections in ONE launch: z selects weight plane + output plane
    {
        dim3 grid(HDIM / BN, M / BM, 3);
        mma_nt<<<grid, 256, SMEM_BYTES>>>(xh, xl, wh0, wl0,
                                          nullptr, qkvh, qkvl, CDIM, HDIM,
                                          0, (long)NWH, (long)NTH, 0, 0, 1);
    }

    const __nv_bfloat16 *qh = qkvh,           *ql = qkvl;
    const __nv_bfloat16 *kh = qkvh + NTH,     *kl = qkvl + NTH;
    const __nv_bfloat16 *vh = qkvh + 2 * NTH, *vl = qkvl + 2 * NTH;

    // S = Q K^T (causal tiles only), f32 out
    {
        dim3 grid(TDIM / BN, TDIM / BM, BDIM);
        mma_nt<<<grid, 256, SMEM_BYTES>>>(qh, ql, kh, kl, s, nullptr, nullptr,
                                          HDIM, TDIM, (long)TDIM * HDIM, (long)TDIM * HDIM,
                                          (long)TDIM * TDIM, 1, 0, 0);
    }

    // softmax -> P planes
    {
        dim3 grid(TDIM, BDIM);
        softmax_causal<<<grid, 256>>>(s, ph, pl, 1.0f / sqrtf((float)HDIM));
    }

    // V^T planes
    {
        dim3 grid(TDIM / 32, HDIM / 32, BDIM);
        transpose_bth<<<grid, dim3(32, 8)>>>(vh, vl, vth, vtl);
    }

    // O = P V (k clamped to diagonal), f32 out
    {
        dim3 grid(HDIM / BN, TDIM / BM, BDIM);
        mma_nt<<<grid, 256, SMEM_BYTES>>>(ph, pl, vth, vtl, out, nullptr, nullptr,
                                          TDIM, HDIM, (long)TDIM * TDIM, (long)TDIM * HDIM,
                                          (long)TDIM * HDIM, 0, 1, 0);
    }
}

// round 15
// speedup vs baseline: 1.1306x; 1.1306x over previous
#include <cuda_runtime.h>
#include <cuda_bf16.h>
#include <cstdint>
#include <math.h>

#define BDIM 4
#define TDIM 2048
#define CDIM 1024
#define HDIM 2048

#define BM 128
#define BN 128
#define BK 32
#define SPADH 40                 // bf16 per smem row (80B: 16B-aligned, LDSM conflict-free)
#define TILE_E (BM * SPADH)      // bf16 elems per tile buffer
#define TILE_B (TILE_E * 2)      // bytes per tile buffer
#define SMEM_BYTES (2 * 4 * TILE_B)   // 2 stages x 4 tiles x 10240B = 81920 -> 2 CTAs/SM

// ---- global scratch planes (allocation-free rule) ----
#define NXC ((size_t)BDIM * TDIM * CDIM)
#define NWH ((size_t)HDIM * CDIM)
#define NTH ((size_t)BDIM * TDIM * HDIM)
#define NTT ((size_t)BDIM * TDIM * TDIM)
__device__ __nv_bfloat16 g_xh[NXC], g_xl[NXC];
__device__ __nv_bfloat16 g_wh[3][NWH], g_wl[3][NWH];
__device__ __nv_bfloat16 g_qkvh[3 * NTH], g_qkvl[3 * NTH];   // q,k,v planes stacked
__device__ __nv_bfloat16 g_vth[NTH], g_vtl[NTH];
__device__ float g_s[NTT];
__device__ __nv_bfloat16 g_ph[NTT], g_pl[NTT];

// m16n8k16 bf16 MMA (sm_80+ baseline PTX)
__device__ __forceinline__ void mma_bf16(float* c, const uint32_t* a, const uint32_t* b) {
    asm volatile(
        "mma.sync.aligned.m16n8k16.row.col.f32.bf16.bf16.f32 "
        "{%0,%1,%2,%3}, {%4,%5,%6,%7}, {%8,%9}, {%0,%1,%2,%3};"
        : "+f"(c[0]), "+f"(c[1]), "+f"(c[2]), "+f"(c[3])
        : "r"(a[0]), "r"(a[1]), "r"(a[2]), "r"(a[3]), "r"(b[0]), "r"(b[1]));
}

__device__ __forceinline__ void ldsm_x4(uint32_t* r, uint32_t addr) {
    asm volatile("ldmatrix.sync.aligned.m8n8.x4.shared.b16 {%0,%1,%2,%3}, [%4];"
                 : "=r"(r[0]), "=r"(r[1]), "=r"(r[2]), "=r"(r[3]) : "r"(addr));
}

#define CP_COMMIT() asm volatile("cp.async.commit_group;" ::: "memory")
#define CP_WAIT0()  asm volatile("cp.async.wait_group 0;" ::: "memory")

// ---------------- 3xBF16 NT GEMM, 2-buffer cp.async, single sync/stage ----------------
// C[m,n] = sum_k A[m*K+k]*B[n*K+k], A/B given as hi/lo bf16 planes (K-major).
// split=0: write f32 to Cf.  split=1: write hi/lo bf16 planes Ch/Cl.
__global__ __launch_bounds__(256, 2) void mma_nt(
    const __nv_bfloat16* __restrict__ Ah, const __nv_bfloat16* __restrict__ Al,
    const __nv_bfloat16* __restrict__ Bh, const __nv_bfloat16* __restrict__ Bl,
    float* __restrict__ Cf, __nv_bfloat16* __restrict__ Ch, __nv_bfloat16* __restrict__ Cl,
    int K, int ldc, long sA, long sB, long sC, int causal, int clampk, int split)
{
    const int m0 = blockIdx.y * BM;
    const int n0 = blockIdx.x * BN;
    if (causal && n0 > m0) return;

    const int b = blockIdx.z;
    Ah += (long)b * sA;  Al += (long)b * sA;
    Bh += (long)b * sB;  Bl += (long)b * sB;

    extern __shared__ __nv_bfloat16 sm[];
    const uint32_t smb = (uint32_t)__cvta_generic_to_shared(sm);

    const int tid  = threadIdx.x;
    const int wid  = tid >> 5;
    const int lane = tid & 31;
    const int g  = lane >> 2;
    const int tg = lane & 3;
    const int wm = (wid >> 2) * 64;
    const int wn = (wid & 3) * 32;

    // LDSM per-thread source addresses (bytes)
    const uint32_t a_base = smb + (uint32_t)(((wm + (lane & 15)) * SPADH + ((lane >> 4) << 3)) * 2);
    const uint32_t b_base = smb + (uint32_t)(((wn + ((lane >> 4) << 3) + (lane & 7)) * SPADH
                                              + (((lane >> 3) & 1) << 3)) * 2);

    const int kEnd = clampk ? (m0 + BM) : K;
    const int nstages = kEnd / BK;

    // cp.async chunk coords (2 chunks of 16B per tile per thread)
    const int r0c = tid >> 2,          c0c = tid & 3;
    const int r1c = (tid + 256) >> 2,  c1c = (tid + 256) & 3;

    const __nv_bfloat16* planes[4] = {Ah, Al, Bh, Bl};
    const int rbase[4] = {m0, m0, n0, n0};

    auto load_stage = [&](int buf, int k0) {
        #pragma unroll
        for (int p = 0; p < 4; p++) {
            __nv_bfloat16* tb = sm + (buf * 4 + p) * TILE_E;
            {
                uint32_t dst = (uint32_t)__cvta_generic_to_shared(tb + r0c * SPADH + c0c * 8);
                const void* src = planes[p] + (long)(rbase[p] + r0c) * K + k0 + c0c * 8;
                asm volatile("cp.async.cg.shared.global [%0], [%1], 16;" :: "r"(dst), "l"(src));
            }
            {
                uint32_t dst = (uint32_t)__cvta_generic_to_shared(tb + r1c * SPADH + c1c * 8);
                const void* src = planes[p] + (long)(rbase[p] + r1c) * K + k0 + c1c * 8;
                asm volatile("cp.async.cg.shared.global [%0], [%1], 16;" :: "r"(dst), "l"(src));
            }
        }
        CP_COMMIT();
    };

    float acc[4][4][4] = {};

    load_stage(0, 0);

    for (int s = 0; s < nstages; s++) {
        CP_WAIT0();          // only load(s) is outstanding here
        __syncthreads();     // stage s visible to all; proves compute(s-1) done by all
        if (s + 1 < nstages) load_stage((s + 1) & 1, (s + 1) * BK);  // overlaps compute(s)

        const uint32_t tAh = (uint32_t)(((s & 1) * 4 + 0) * TILE_B);
        const uint32_t tAl = (uint32_t)(((s & 1) * 4 + 1) * TILE_B);
        const uint32_t tBh = (uint32_t)(((s & 1) * 4 + 2) * TILE_B);
        const uint32_t tBl = (uint32_t)(((s & 1) * 4 + 3) * TILE_B);

        #pragma unroll
        for (int ks = 0; ks < BK; ks += 16) {
            const uint32_t ksb = (uint32_t)(ks * 2);
            uint32_t af[4][4], bh[2][4];

            // Phase 1: ah * bh
            #pragma unroll
            for (int mt = 0; mt < 4; mt++)
                ldsm_x4(af[mt], a_base + tAh + (uint32_t)(mt * 16 * SPADH * 2) + ksb);
            #pragma unroll
            for (int p = 0; p < 2; p++)
                ldsm_x4(bh[p], b_base + tBh + (uint32_t)(p * 16 * SPADH * 2) + ksb);
            #pragma unroll
            for (int mt = 0; mt < 4; mt++)
                #pragma unroll
                for (int nt = 0; nt < 4; nt++)
                    mma_bf16(acc[mt][nt], af[mt], &bh[nt >> 1][(nt & 1) * 2]);

            // Phase 2: ah * bl
            uint32_t bl[2][4];
            #pragma unroll
            for (int p = 0; p < 2; p++)
                ldsm_x4(bl[p], b_base + tBl + (uint32_t)(p * 16 * SPADH * 2) + ksb);
            #pragma unroll
            for (int mt = 0; mt < 4; mt++)
                #pragma unroll
                for (int nt = 0; nt < 4; nt++)
                    mma_bf16(acc[mt][nt], af[mt], &bl[nt >> 1][(nt & 1) * 2]);

            // Phase 3: al * bh (reuse af regs for Al)
            #pragma unroll
            for (int mt = 0; mt < 4; mt++)
                ldsm_x4(af[mt], a_base + tAl + (uint32_t)(mt * 16 * SPADH * 2) + ksb);
            #pragma unroll
            for (int mt = 0; mt < 4; mt++)
                #pragma unroll
                for (int nt = 0; nt < 4; nt++)
                    mma_bf16(acc[mt][nt], af[mt], &bh[nt >> 1][(nt & 1) * 2]);
        }
    }

    // ---- epilogue ----
    if (split) {
        Ch += (long)blockIdx.z * sC;  Cl += (long)blockIdx.z * sC;
        #pragma unroll
        for (int mt = 0; mt < 4; mt++) {
            #pragma unroll
            for (int nt = 0; nt < 4; nt++) {
                const int row = m0 + wm + mt * 16 + g;
                const int col = n0 + wn + nt * 8 + tg * 2;
                #pragma unroll
                for (int h = 0; h < 2; h++) {
                    float2 v = {acc[mt][nt][2 * h], acc[mt][nt][2 * h + 1]};
                    __nv_bfloat162 hp = __float22bfloat162_rn(v);
                    __nv_bfloat162 lp = __float22bfloat162_rn(make_float2(
                        v.x - __bfloat162float(hp.x), v.y - __bfloat162float(hp.y)));
                    long off = (long)(row + 8 * h) * ldc + col;
                    *(__nv_bfloat162*)&Ch[off] = hp;
                    *(__nv_bfloat162*)&Cl[off] = lp;
                }
            }
        }
    } else {
        Cf += (long)blockIdx.z * sC;
        #pragma unroll
        for (int mt = 0; mt < 4; mt++) {
            #pragma unroll
            for (int nt = 0; nt < 4; nt++) {
                const int row = m0 + wm + mt * 16 + g;
                const int col = n0 + wn + nt * 8 + tg * 2;
                float2 lo = {acc[mt][nt][0], acc[mt][nt][1]};
                float2 hi = {acc[mt][nt][2], acc[mt][nt][3]};
                *(float2*)&Cf[(long)row * ldc + col] = lo;
                *(float2*)&Cf[(long)(row + 8) * ldc + col] = hi;
            }
        }
    }
}

// ---------------- f32 -> hi/lo bf16 planes ----------------
__global__ __launch_bounds__(256) void split_f32(
    const float* __restrict__ src, __nv_bfloat16* __restrict__ h,
    __nv_bfloat16* __restrict__ l, long n4)
{
    long i = ((long)blockIdx.x * 256 + threadIdx.x);
    if (i >= n4) return;
    float4 v = *(const float4*)(src + i * 4);
    __nv_bfloat162 h01 = __float22bfloat162_rn(make_float2(v.x, v.y));
    __nv_bfloat162 h23 = __float22bfloat162_rn(make_float2(v.z, v.w));
    __nv_bfloat162 l01 = __float22bfloat162_rn(make_float2(
        v.x - __bfloat162float(h01.x), v.y - __bfloat162float(h01.y)));
    __nv_bfloat162 l23 = __float22bfloat162_rn(make_float2(
        v.z - __bfloat162float(h23.x), v.w - __bfloat162float(h23.y)));
    *(__nv_bfloat162*)&h[i * 4]     = h01;
    *(__nv_bfloat162*)&h[i * 4 + 2] = h23;
    *(__nv_bfloat162*)&l[i * 4]     = l01;
    *(__nv_bfloat162*)&l[i * 4 + 2] = l23;
}

// ---------------- causal softmax -> hi/lo bf16 P planes ----------------
__global__ __launch_bounds__(256) void softmax_causal(
    const float* __restrict__ S, __nv_bfloat16* __restrict__ Ph,
    __nv_bfloat16* __restrict__ Pl, float scale)
{
    const int t = blockIdx.x;
    const int b = blockIdx.y;
    const long ro = ((long)b * TDIM + t) * TDIM;
    const float* row = S + ro;
    const int n = t + 1;
    const int nend = ((t >> 7) + 1) << 7;
    const int tid = threadIdx.x;

    __shared__ float red[256];

    float mx = -INFINITY;
    for (int i = tid; i < n; i += 256) mx = fmaxf(mx, row[i] * scale);
    red[tid] = mx;
    __syncthreads();
    for (int s = 128; s > 0; s >>= 1) {
        if (tid < s) red[tid] = fmaxf(red[tid], red[tid + s]);
        __syncthreads();
    }
    mx = red[0];
    __syncthreads();

    float sum = 0.f;
    for (int i = tid; i < n; i += 256) sum += __expf(row[i] * scale - mx);
    red[tid] = sum;
    __syncthreads();
    for (int s = 128; s > 0; s >>= 1) {
        if (tid < s) red[tid] += red[tid + s];
        __syncthreads();
    }
    const float inv = 1.0f / red[0];

    for (int i = tid; i < n; i += 256) {
        float p = __expf(row[i] * scale - mx) * inv;
        __nv_bfloat16 hp = __float2bfloat16_rn(p);
        Ph[ro + i] = hp;
        Pl[ro + i] = __float2bfloat16_rn(p - __bfloat162float(hp));
    }
    const __nv_bfloat16 z = __float2bfloat16_rn(0.f);
    for (int i = n + tid; i < nend; i += 256) { Ph[ro + i] = z; Pl[ro + i] = z; }
}

// ---------------- transpose both V planes: vt[b][h][t] = v[b][t][h] ----------------
__global__ __launch_bounds__(256) void transpose_bth(
    const __nv_bfloat16* __restrict__ Vh, const __nv_bfloat16* __restrict__ Vl,
    __nv_bfloat16* __restrict__ VTh, __nv_bfloat16* __restrict__ VTl)
{
    __shared__ __nv_bfloat16 th[32][33], tl[32][33];
    const int b = blockIdx.z;
    const int t0 = blockIdx.x * 32;
    const int h0 = blockIdx.y * 32;
    const int tx = threadIdx.x, ty = threadIdx.y;   // 32 x 8

    const long vo = (long)b * TDIM * HDIM;

    #pragma unroll
    for (int i = 0; i < 4; i++) {
        long src = vo + (long)(t0 + ty + 8 * i) * HDIM + h0 + tx;
        th[ty + 8 * i][tx] = Vh[src];
        tl[ty + 8 * i][tx] = Vl[src];
    }
    __syncthreads();
    #pragma unroll
    for (int i = 0; i < 4; i++) {
        long dst = vo + (long)(h0 + ty + 8 * i) * TDIM + t0 + tx;
        VTh[dst] = th[tx][ty + 8 * i];
        VTl[dst] = tl[tx][ty + 8 * i];
    }
}

// ---------------- driver ----------------
extern "C" void kernel_launch(void* const* d_in, const int* in_sizes, int n_in,
                              void* d_out, int out_size)
{
    const float* x  = (const float*)d_in[0];
    const float* Wk = (const float*)d_in[1];
    const float* Wq = (const float*)d_in[2];
    const float* Wv = (const float*)d_in[3];
    float* out = (float*)d_out;

    __nv_bfloat16 *xh, *xl, *wh0, *wl0, *qkvh, *qkvl, *vth, *vtl, *ph, *pl;
    float* s;
    cudaGetSymbolAddress((void**)&xh,   g_xh);    cudaGetSymbolAddress((void**)&xl,   g_xl);
    cudaGetSymbolAddress((void**)&wh0,  g_wh);    cudaGetSymbolAddress((void**)&wl0,  g_wl);
    cudaGetSymbolAddress((void**)&qkvh, g_qkvh);  cudaGetSymbolAddress((void**)&qkvl, g_qkvl);
    cudaGetSymbolAddress((void**)&vth,  g_vth);   cudaGetSymbolAddress((void**)&vtl,  g_vtl);
    cudaGetSymbolAddress((void**)&ph,   g_ph);    cudaGetSymbolAddress((void**)&pl,   g_pl);
    cudaGetSymbolAddress((void**)&s,    g_s);

    cudaFuncSetAttribute(mma_nt, cudaFuncAttributeMaxDynamicSharedMemorySize, SMEM_BYTES);

    const int M = BDIM * TDIM;   // 8192

    // split inputs into hi/lo bf16 planes (weight order: q, k, v)
    {
        long nx4 = NXC / 4, nw4 = NWH / 4;
        split_f32<<<(unsigned)((nx4 + 255) / 256), 256>>>(x, xh, xl, nx4);
        split_f32<<<(unsigned)((nw4 + 255) / 256), 256>>>(Wq, wh0 + 0 * NWH, wl0 + 0 * NWH, nw4);
        split_f32<<<(unsigned)((nw4 + 255) / 256), 256>>>(Wk, wh0 + 1 * NWH, wl0 + 1 * NWH, nw4);
        split_f32<<<(unsigned)((nw4 + 255) / 256), 256>>>(Wv, wh0 + 2 * NWH, wl0 + 2 * NWH, nw4);
    }

    // All three projections in ONE launch: z selects weight plane + output plane
    {
        dim3 grid(HDIM / BN, M / BM, 3);
        mma_nt<<<grid, 256, SMEM_BYTES>>>(xh, xl, wh0, wl0,
                                          nullptr, qkvh, qkvl, CDIM, HDIM,
                                          0, (long)NWH, (long)NTH, 0, 0, 1);
    }

    const __nv_bfloat16 *qh = qkvh,           *ql = qkvl;
    const __nv_bfloat16 *kh = qkvh + NTH,     *kl = qkvl + NTH;
    const __nv_bfloat16 *vh = qkvh + 2 * NTH, *vl = qkvl + 2 * NTH;

    // S = Q K^T (causal tiles only), f32 out
    {
        dim3 grid(TDIM / BN, TDIM / BM, BDIM);
        mma_nt<<<grid, 256, SMEM_BYTES>>>(qh, ql, kh, kl, s, nullptr, nullptr,
                                          HDIM, TDIM, (long)TDIM * HDIM, (long)TDIM * HDIM,
                                          (long)TDIM * TDIM, 1, 0, 0);
    }

    // softmax -> P planes
    {
        dim3 grid(TDIM, BDIM);
        softmax_causal<<<grid, 256>>>(s, ph, pl, 1.0f / sqrtf((float)HDIM));
    }

    // V^T planes
    {
        dim3 grid(TDIM / 32, HDIM / 32, BDIM);
        transpose_bth<<<grid, dim3(32, 8)>>>(vh, vl, vth, vtl);
    }

    // O = P V (k clamped to diagonal), f32 out
    {
        dim3 grid(HDIM / BN, TDIM / BM, BDIM);
        mma_nt<<<grid, 256, SMEM_BYTES>>>(ph, pl, vth, vtl, out, nullptr, nullptr,
                                          TDIM, HDIM, (long)TDIM * TDIM, (long)TDIM * HDIM,
                                          (long)TDIM * HDIM, 0, 1, 0);
    }
}

// round 16
// speedup vs baseline: 1.1899x; 1.0524x over previous
#include <cuda_runtime.h>
#include <cuda_bf16.h>
#include <cstdint>
#include <math.h>

#define BDIM 4
#define TDIM 2048
#define CDIM 1024
#define HDIM 2048

#define BM 128
#define BN 128
#define BK 32
#define SPADH 40                 // bf16 per smem row (80B, LDSM conflict-free)
#define TILE_E (BM * SPADH)      // bf16 elems per A/B tile buffer (NT kernel)
#define TILE_B (TILE_E * 2)
#define SMEM_BYTES (2 * 4 * TILE_B)   // 81920 -> 2 CTAs/SM

// PV kernel: B staged row-major [k][n], 32 x 136 bf16
#define SPADB 136
#define PV_A_E (BM * SPADH)      // 5120 elems
#define PV_B_E (BK * SPADB)      // 4352 elems
#define PV_STAGE_E (2 * PV_A_E + 2 * PV_B_E)   // 18944 elems
#define PV_SMEM_BYTES (2 * PV_STAGE_E * 2)     // 75776 bytes

// ---- global scratch planes (allocation-free rule) ----
#define NXC ((size_t)BDIM * TDIM * CDIM)
#define NWH ((size_t)HDIM * CDIM)
#define NTH ((size_t)BDIM * TDIM * HDIM)
#define NTT ((size_t)BDIM * TDIM * TDIM)
__device__ __nv_bfloat16 g_xh[NXC], g_xl[NXC];
__device__ __nv_bfloat16 g_wh[3][NWH], g_wl[3][NWH];
__device__ __nv_bfloat16 g_qkvh[3 * NTH], g_qkvl[3 * NTH];   // q,k,v planes stacked
__device__ float g_s[NTT];
__device__ __nv_bfloat16 g_ph[NTT], g_pl[NTT];

// m16n8k16 bf16 MMA (sm_80+ baseline PTX)
__device__ __forceinline__ void mma_bf16(float* c, const uint32_t* a, const uint32_t* b) {
    asm volatile(
        "mma.sync.aligned.m16n8k16.row.col.f32.bf16.bf16.f32 "
        "{%0,%1,%2,%3}, {%4,%5,%6,%7}, {%8,%9}, {%0,%1,%2,%3};"
        : "+f"(c[0]), "+f"(c[1]), "+f"(c[2]), "+f"(c[3])
        : "r"(a[0]), "r"(a[1]), "r"(a[2]), "r"(a[3]), "r"(b[0]), "r"(b[1]));
}

__device__ __forceinline__ void ldsm_x4(uint32_t* r, uint32_t addr) {
    asm volatile("ldmatrix.sync.aligned.m8n8.x4.shared.b16 {%0,%1,%2,%3}, [%4];"
                 : "=r"(r[0]), "=r"(r[1]), "=r"(r[2]), "=r"(r[3]) : "r"(addr));
}

__device__ __forceinline__ void ldsm_x4_t(uint32_t* r, uint32_t addr) {
    asm volatile("ldmatrix.sync.aligned.m8n8.x4.trans.shared.b16 {%0,%1,%2,%3}, [%4];"
                 : "=r"(r[0]), "=r"(r[1]), "=r"(r[2]), "=r"(r[3]) : "r"(addr));
}

#define CP_COMMIT() asm volatile("cp.async.commit_group;" ::: "memory")
#define CP_WAIT0()  asm volatile("cp.async.wait_group 0;" ::: "memory")

// ---------------- 3xBF16 NT GEMM, 2-buffer cp.async, single sync/stage ----------------
__global__ __launch_bounds__(256, 2) void mma_nt(
    const __nv_bfloat16* __restrict__ Ah, const __nv_bfloat16* __restrict__ Al,
    const __nv_bfloat16* __restrict__ Bh, const __nv_bfloat16* __restrict__ Bl,
    float* __restrict__ Cf, __nv_bfloat16* __restrict__ Ch, __nv_bfloat16* __restrict__ Cl,
    int K, int ldc, long sA, long sB, long sC, int causal, int split)
{
    const int m0 = blockIdx.y * BM;
    const int n0 = blockIdx.x * BN;
    if (causal && n0 > m0) return;

    const int b = blockIdx.z;
    Ah += (long)b * sA;  Al += (long)b * sA;
    Bh += (long)b * sB;  Bl += (long)b * sB;

    extern __shared__ __nv_bfloat16 sm[];
    const uint32_t smb = (uint32_t)__cvta_generic_to_shared(sm);

    const int tid  = threadIdx.x;
    const int wid  = tid >> 5;
    const int lane = tid & 31;
    const int g  = lane >> 2;
    const int tg = lane & 3;
    const int wm = (wid >> 2) * 64;
    const int wn = (wid & 3) * 32;

    const uint32_t a_base = smb + (uint32_t)(((wm + (lane & 15)) * SPADH + ((lane >> 4) << 3)) * 2);
    const uint32_t b_base = smb + (uint32_t)(((wn + ((lane >> 4) << 3) + (lane & 7)) * SPADH
                                              + (((lane >> 3) & 1) << 3)) * 2);

    const int nstages = K / BK;

    const int r0c = tid >> 2,          c0c = tid & 3;
    const int r1c = (tid + 256) >> 2,  c1c = (tid + 256) & 3;

    const __nv_bfloat16* planes[4] = {Ah, Al, Bh, Bl};
    const int rbase[4] = {m0, m0, n0, n0};

    auto load_stage = [&](int buf, int k0) {
        #pragma unroll
        for (int p = 0; p < 4; p++) {
            __nv_bfloat16* tb = sm + (buf * 4 + p) * TILE_E;
            {
                uint32_t dst = (uint32_t)__cvta_generic_to_shared(tb + r0c * SPADH + c0c * 8);
                const void* src = planes[p] + (long)(rbase[p] + r0c) * K + k0 + c0c * 8;
                asm volatile("cp.async.cg.shared.global [%0], [%1], 16;" :: "r"(dst), "l"(src));
            }
            {
                uint32_t dst = (uint32_t)__cvta_generic_to_shared(tb + r1c * SPADH + c1c * 8);
                const void* src = planes[p] + (long)(rbase[p] + r1c) * K + k0 + c1c * 8;
                asm volatile("cp.async.cg.shared.global [%0], [%1], 16;" :: "r"(dst), "l"(src));
            }
        }
        CP_COMMIT();
    };

    float acc[4][4][4] = {};

    load_stage(0, 0);

    for (int s = 0; s < nstages; s++) {
        CP_WAIT0();
        __syncthreads();
        if (s + 1 < nstages) load_stage((s + 1) & 1, (s + 1) * BK);

        const uint32_t tAh = (uint32_t)(((s & 1) * 4 + 0) * TILE_B);
        const uint32_t tAl = (uint32_t)(((s & 1) * 4 + 1) * TILE_B);
        const uint32_t tBh = (uint32_t)(((s & 1) * 4 + 2) * TILE_B);
        const uint32_t tBl = (uint32_t)(((s & 1) * 4 + 3) * TILE_B);

        #pragma unroll
        for (int ks = 0; ks < BK; ks += 16) {
            const uint32_t ksb = (uint32_t)(ks * 2);
            uint32_t af[4][4], bh[2][4];

            #pragma unroll
            for (int mt = 0; mt < 4; mt++)
                ldsm_x4(af[mt], a_base + tAh + (uint32_t)(mt * 16 * SPADH * 2) + ksb);
            #pragma unroll
            for (int p = 0; p < 2; p++)
                ldsm_x4(bh[p], b_base + tBh + (uint32_t)(p * 16 * SPADH * 2) + ksb);
            #pragma unroll
            for (int mt = 0; mt < 4; mt++)
                #pragma unroll
                for (int nt = 0; nt < 4; nt++)
                    mma_bf16(acc[mt][nt], af[mt], &bh[nt >> 1][(nt & 1) * 2]);

            uint32_t bl[2][4];
            #pragma unroll
            for (int p = 0; p < 2; p++)
                ldsm_x4(bl[p], b_base + tBl + (uint32_t)(p * 16 * SPADH * 2) + ksb);
            #pragma unroll
            for (int mt = 0; mt < 4; mt++)
                #pragma unroll
                for (int nt = 0; nt < 4; nt++)
                    mma_bf16(acc[mt][nt], af[mt], &bl[nt >> 1][(nt & 1) * 2]);

            #pragma unroll
            for (int mt = 0; mt < 4; mt++)
                ldsm_x4(af[mt], a_base + tAl + (uint32_t)(mt * 16 * SPADH * 2) + ksb);
            #pragma unroll
            for (int mt = 0; mt < 4; mt++)
                #pragma unroll
                for (int nt = 0; nt < 4; nt++)
                    mma_bf16(acc[mt][nt], af[mt], &bh[nt >> 1][(nt & 1) * 2]);
        }
    }

    if (split) {
        Ch += (long)blockIdx.z * sC;  Cl += (long)blockIdx.z * sC;
        #pragma unroll
        for (int mt = 0; mt < 4; mt++) {
            #pragma unroll
            for (int nt = 0; nt < 4; nt++) {
                const int row = m0 + wm + mt * 16 + g;
                const int col = n0 + wn + nt * 8 + tg * 2;
                #pragma unroll
                for (int h = 0; h < 2; h++) {
                    float2 v = {acc[mt][nt][2 * h], acc[mt][nt][2 * h + 1]};
                    __nv_bfloat162 hp = __float22bfloat162_rn(v);
                    __nv_bfloat162 lp = __float22bfloat162_rn(make_float2(
                        v.x - __bfloat162float(hp.x), v.y - __bfloat162float(hp.y)));
                    long off = (long)(row + 8 * h) * ldc + col;
                    *(__nv_bfloat162*)&Ch[off] = hp;
                    *(__nv_bfloat162*)&Cl[off] = lp;
                }
            }
        }
    } else {
        Cf += (long)blockIdx.z * sC;
        #pragma unroll
        for (int mt = 0; mt < 4; mt++) {
            #pragma unroll
            for (int nt = 0; nt < 4; nt++) {
                const int row = m0 + wm + mt * 16 + g;
                const int col = n0 + wn + nt * 8 + tg * 2;
                float2 lo = {acc[mt][nt][0], acc[mt][nt][1]};
                float2 hi = {acc[mt][nt][2], acc[mt][nt][3]};
                *(float2*)&Cf[(long)row * ldc + col] = lo;
                *(float2*)&Cf[(long)(row + 8) * ldc + col] = hi;
            }
        }
    }
}

// ---------------- PV GEMM: A = P planes (NT), B = V planes row-major [k][n] ----------------
// O[t,h] = sum_s P[t,s] * V[s,h]; B fragments via ldmatrix.trans. K clamped to m0+BM.
__global__ __launch_bounds__(256, 2) void mma_pv(
    const __nv_bfloat16* __restrict__ Ph, const __nv_bfloat16* __restrict__ Pl,
    const __nv_bfloat16* __restrict__ Vh, const __nv_bfloat16* __restrict__ Vl,
    float* __restrict__ O)
{
    const int m0 = blockIdx.y * BM;
    const int n0 = blockIdx.x * BN;
    const int b = blockIdx.z;
    Ph += (long)b * TDIM * TDIM;  Pl += (long)b * TDIM * TDIM;
    Vh += (long)b * TDIM * HDIM;  Vl += (long)b * TDIM * HDIM;
    O  += (long)b * TDIM * HDIM;

    extern __shared__ __nv_bfloat16 sm[];
    const uint32_t smb = (uint32_t)__cvta_generic_to_shared(sm);

    const int tid  = threadIdx.x;
    const int wid  = tid >> 5;
    const int lane = tid & 31;
    const int g  = lane >> 2;
    const int tg = lane & 3;
    const int wm = (wid >> 2) * 64;
    const int wn = (wid & 3) * 32;

    // A LDSM base (NT layout, SPADH rows)
    const uint32_t a_base = smb + (uint32_t)(((wm + (lane & 15)) * SPADH + ((lane >> 4) << 3)) * 2);
    // B trans-LDSM base: matrices {k0-7,n0-7},{k8-15,n0-7},{k0-7,n8-15},{k8-15,n8-15}
    const uint32_t b_base = smb + (uint32_t)(((((lane >> 3) & 1) * 8 + (lane & 7)) * SPADB
                                              + wn + ((lane >> 4) << 3)) * 2);

    const int kEnd = m0 + BM;            // causal clamp (P zero beyond)
    const int nstages = kEnd / BK;

    // A staging coords (2 x 16B chunks per plane per thread)
    const int r0c = tid >> 2,          c0c = tid & 3;
    const int r1c = (tid + 256) >> 2,  c1c = (tid + 256) & 3;
    // B staging coords: chunk c in 0..511: row=c>>4 (k), col8=(c&15)*8 (n)
    const int br0 = tid >> 4,          bc0 = tid & 15;
    const int br1 = (tid + 256) >> 4,  bc1 = (tid + 256) & 15;

    auto load_stage = [&](int buf, int k0) {
        const uint32_t sb = (uint32_t)(buf * PV_STAGE_E);
        // A planes (Ph, Pl)
        const __nv_bfloat16* aps[2] = {Ph, Pl};
        #pragma unroll
        for (int p = 0; p < 2; p++) {
            uint32_t tb = sb + (uint32_t)(p * PV_A_E);
            {
                uint32_t dst = smb + (tb + (uint32_t)(r0c * SPADH + c0c * 8)) * 2;
                const void* src = aps[p] + (long)(m0 + r0c) * TDIM + k0 + c0c * 8;
                asm volatile("cp.async.cg.shared.global [%0], [%1], 16;" :: "r"(dst), "l"(src));
            }
            {
                uint32_t dst = smb + (tb + (uint32_t)(r1c * SPADH + c1c * 8)) * 2;
                const void* src = aps[p] + (long)(m0 + r1c) * TDIM + k0 + c1c * 8;
                asm volatile("cp.async.cg.shared.global [%0], [%1], 16;" :: "r"(dst), "l"(src));
            }
        }
        // B planes (Vh, Vl), row-major [k][n]
        const __nv_bfloat16* bps[2] = {Vh, Vl};
        #pragma unroll
        for (int p = 0; p < 2; p++) {
            uint32_t tb = sb + (uint32_t)(2 * PV_A_E + p * PV_B_E);
            {
                uint32_t dst = smb + (tb + (uint32_t)(br0 * SPADB + bc0 * 8)) * 2;
                const void* src = bps[p] + (long)(k0 + br0) * HDIM + n0 + bc0 * 8;
                asm volatile("cp.async.cg.shared.global [%0], [%1], 16;" :: "r"(dst), "l"(src));
            }
            {
                uint32_t dst = smb + (tb + (uint32_t)(br1 * SPADB + bc1 * 8)) * 2;
                const void* src = bps[p] + (long)(k0 + br1) * HDIM + n0 + bc1 * 8;
                asm volatile("cp.async.cg.shared.global [%0], [%1], 16;" :: "r"(dst), "l"(src));
            }
        }
        CP_COMMIT();
    };

    float acc[4][4][4] = {};

    load_stage(0, 0);

    for (int s = 0; s < nstages; s++) {
        CP_WAIT0();
        __syncthreads();
        if (s + 1 < nstages) load_stage((s + 1) & 1, (s + 1) * BK);

        const uint32_t sb  = (uint32_t)((s & 1) * PV_STAGE_E * 2);   // bytes
        const uint32_t tAh = sb;
        const uint32_t tAl = sb + (uint32_t)(PV_A_E * 2);
        const uint32_t tBh = sb + (uint32_t)(2 * PV_A_E * 2);
        const uint32_t tBl = sb + (uint32_t)((2 * PV_A_E + PV_B_E) * 2);

        #pragma unroll
        for (int ks = 0; ks < BK; ks += 16) {
            const uint32_t ksa = (uint32_t)(ks * 2);
            const uint32_t ksb = (uint32_t)(ks * SPADB * 2);   // B: advance 16 k-rows
            uint32_t af[4][4], bh[2][4];

            #pragma unroll
            for (int mt = 0; mt < 4; mt++)
                ldsm_x4(af[mt], a_base + tAh + (uint32_t)(mt * 16 * SPADH * 2) + ksa);
            #pragma unroll
            for (int p = 0; p < 2; p++)
                ldsm_x4_t(bh[p], b_base + tBh + (uint32_t)(p * 16 * 2) + ksb);
            #pragma unroll
            for (int mt = 0; mt < 4; mt++)
                #pragma unroll
                for (int nt = 0; nt < 4; nt++)
                    mma_bf16(acc[mt][nt], af[mt], &bh[nt >> 1][(nt & 1) * 2]);

            uint32_t bl[2][4];
            #pragma unroll
            for (int p = 0; p < 2; p++)
                ldsm_x4_t(bl[p], b_base + tBl + (uint32_t)(p * 16 * 2) + ksb);
            #pragma unroll
            for (int mt = 0; mt < 4; mt++)
                #pragma unroll
                for (int nt = 0; nt < 4; nt++)
                    mma_bf16(acc[mt][nt], af[mt], &bl[nt >> 1][(nt & 1) * 2]);

            #pragma unroll
            for (int mt = 0; mt < 4; mt++)
                ldsm_x4(af[mt], a_base + tAl + (uint32_t)(mt * 16 * SPADH * 2) + ksa);
            #pragma unroll
            for (int mt = 0; mt < 4; mt++)
                #pragma unroll
                for (int nt = 0; nt < 4; nt++)
                    mma_bf16(acc[mt][nt], af[mt], &bh[nt >> 1][(nt & 1) * 2]);
        }
    }

    #pragma unroll
    for (int mt = 0; mt < 4; mt++) {
        #pragma unroll
        for (int nt = 0; nt < 4; nt++) {
            const int row = m0 + wm + mt * 16 + g;
            const int col = n0 + wn + nt * 8 + tg * 2;
            float2 lo = {acc[mt][nt][0], acc[mt][nt][1]};
            float2 hi = {acc[mt][nt][2], acc[mt][nt][3]};
            *(float2*)&O[(long)row * HDIM + col] = lo;
            *(float2*)&O[(long)(row + 8) * HDIM + col] = hi;
        }
    }
}

// ---------------- f32 -> hi/lo bf16 planes ----------------
__global__ __launch_bounds__(256) void split_f32(
    const float* __restrict__ src, __nv_bfloat16* __restrict__ h,
    __nv_bfloat16* __restrict__ l, long n4)
{
    long i = ((long)blockIdx.x * 256 + threadIdx.x);
    if (i >= n4) return;
    float4 v = *(const float4*)(src + i * 4);
    __nv_bfloat162 h01 = __float22bfloat162_rn(make_float2(v.x, v.y));
    __nv_bfloat162 h23 = __float22bfloat162_rn(make_float2(v.z, v.w));
    __nv_bfloat162 l01 = __float22bfloat162_rn(make_float2(
        v.x - __bfloat162float(h01.x), v.y - __bfloat162float(h01.y)));
    __nv_bfloat162 l23 = __float22bfloat162_rn(make_float2(
        v.z - __bfloat162float(h23.x), v.w - __bfloat162float(h23.y)));
    *(__nv_bfloat162*)&h[i * 4]     = h01;
    *(__nv_bfloat162*)&h[i * 4 + 2] = h23;
    *(__nv_bfloat162*)&l[i * 4]     = l01;
    *(__nv_bfloat162*)&l[i * 4 + 2] = l23;
}

// all three W splits in one launch (z selects source)
__global__ __launch_bounds__(256) void split_w3(
    const float* __restrict__ W0, const float* __restrict__ W1, const float* __restrict__ W2,
    __nv_bfloat16* __restrict__ h, __nv_bfloat16* __restrict__ l, long n4)
{
    const float* srcs[3] = {W0, W1, W2};
    const float* src = srcs[blockIdx.y];
    h += (long)blockIdx.y * NWH;
    l += (long)blockIdx.y * NWH;
    long i = ((long)blockIdx.x * 256 + threadIdx.x);
    if (i >= n4) return;
    float4 v = *(const float4*)(src + i * 4);
    __nv_bfloat162 h01 = __float22bfloat162_rn(make_float2(v.x, v.y));
    __nv_bfloat162 h23 = __float22bfloat162_rn(make_float2(v.z, v.w));
    __nv_bfloat162 l01 = __float22bfloat162_rn(make_float2(
        v.x - __bfloat162float(h01.x), v.y - __bfloat162float(h01.y)));
    __nv_bfloat162 l23 = __float22bfloat162_rn(make_float2(
        v.z - __bfloat162float(h23.x), v.w - __bfloat162float(h23.y)));
    *(__nv_bfloat162*)&h[i * 4]     = h01;
    *(__nv_bfloat162*)&h[i * 4 + 2] = h23;
    *(__nv_bfloat162*)&l[i * 4]     = l01;
    *(__nv_bfloat162*)&l[i * 4 + 2] = l23;
}

// ---------------- causal softmax -> hi/lo bf16 P planes ----------------
__global__ __launch_bounds__(256) void softmax_causal(
    const float* __restrict__ S, __nv_bfloat16* __restrict__ Ph,
    __nv_bfloat16* __restrict__ Pl, float scale)
{
    const int t = blockIdx.x;
    const int b = blockIdx.y;
    const long ro = ((long)b * TDIM + t) * TDIM;
    const float* row = S + ro;
    const int n = t + 1;
    const int nend = ((t >> 7) + 1) << 7;
    const int tid = threadIdx.x;

    __shared__ float red[256];

    float mx = -INFINITY;
    for (int i = tid; i < n; i += 256) mx = fmaxf(mx, row[i] * scale);
    red[tid] = mx;
    __syncthreads();
    for (int s = 128; s > 0; s >>= 1) {
        if (tid < s) red[tid] = fmaxf(red[tid], red[tid + s]);
        __syncthreads();
    }
    mx = red[0];
    __syncthreads();

    float sum = 0.f;
    for (int i = tid; i < n; i += 256) sum += __expf(row[i] * scale - mx);
    red[tid] = sum;
    __syncthreads();
    for (int s = 128; s > 0; s >>= 1) {
        if (tid < s) red[tid] += red[tid + s];
        __syncthreads();
    }
    const float inv = 1.0f / red[0];

    for (int i = tid; i < n; i += 256) {
        float p = __expf(row[i] * scale - mx) * inv;
        __nv_bfloat16 hp = __float2bfloat16_rn(p);
        Ph[ro + i] = hp;
        Pl[ro + i] = __float2bfloat16_rn(p - __bfloat162float(hp));
    }
    const __nv_bfloat16 z = __float2bfloat16_rn(0.f);
    for (int i = n + tid; i < nend; i += 256) { Ph[ro + i] = z; Pl[ro + i] = z; }
}

// ---------------- driver ----------------
extern "C" void kernel_launch(void* const* d_in, const int* in_sizes, int n_in,
                              void* d_out, int out_size)
{
    const float* x  = (const float*)d_in[0];
    const float* Wk = (const float*)d_in[1];
    const float* Wq = (const float*)d_in[2];
    const float* Wv = (const float*)d_in[3];
    float* out = (float*)d_out;

    __nv_bfloat16 *xh, *xl, *wh0, *wl0, *qkvh, *qkvl, *ph, *pl;
    float* s;
    cudaGetSymbolAddress((void**)&xh,   g_xh);    cudaGetSymbolAddress((void**)&xl,   g_xl);
    cudaGetSymbolAddress((void**)&wh0,  g_wh);    cudaGetSymbolAddress((void**)&wl0,  g_wl);
    cudaGetSymbolAddress((void**)&qkvh, g_qkvh);  cudaGetSymbolAddress((void**)&qkvl, g_qkvl);
    cudaGetSymbolAddress((void**)&ph,   g_ph);    cudaGetSymbolAddress((void**)&pl,   g_pl);
    cudaGetSymbolAddress((void**)&s,    g_s);

    cudaFuncSetAttribute(mma_nt, cudaFuncAttributeMaxDynamicSharedMemorySize, SMEM_BYTES);
    cudaFuncSetAttribute(mma_pv, cudaFuncAttributeMaxDynamicSharedMemorySize, PV_SMEM_BYTES);

    const int M = BDIM * TDIM;   // 8192

    // split inputs into hi/lo bf16 planes (weight order: q, k, v)
    {
        long nx4 = NXC / 4, nw4 = NWH / 4;
        split_f32<<<(unsigned)((nx4 + 255) / 256), 256>>>(x, xh, xl, nx4);
        dim3 gw((unsigned)((nw4 + 255) / 256), 3);
        split_w3<<<gw, 256>>>(Wq, Wk, Wv, wh0, wl0, nw4);
    }

    // All three projections in ONE launch: z selects weight plane + output plane
    {
        dim3 grid(HDIM / BN, M / BM, 3);
        mma_nt<<<grid, 256, SMEM_BYTES>>>(xh, xl, wh0, wl0,
                                          nullptr, qkvh, qkvl, CDIM, HDIM,
                                          0, (long)NWH, (long)NTH, 0, 1);
    }

    const __nv_bfloat16 *qh = qkvh,           *ql = qkvl;
    const __nv_bfloat16 *kh = qkvh + NTH,     *kl = qkvl + NTH;
    const __nv_bfloat16 *vh = qkvh + 2 * NTH, *vl = qkvl + 2 * NTH;

    // S = Q K^T (causal tiles only), f32 out
    {
        dim3 grid(TDIM / BN, TDIM / BM, BDIM);
        mma_nt<<<grid, 256, SMEM_BYTES>>>(qh, ql, kh, kl, s, nullptr, nullptr,
                                          HDIM, TDIM, (long)TDIM * HDIM, (long)TDIM * HDIM,
                                          (long)TDIM * TDIM, 1, 0);
    }

    // softmax -> P planes
    {
        dim3 grid(TDIM, BDIM);
        softmax_causal<<<grid, 256>>>(s, ph, pl, 1.0f / sqrtf((float)HDIM));
    }

    // O = P V directly from row-major V planes (ldmatrix.trans), K clamped
    {
        dim3 grid(HDIM / BN, TDIM / BM, BDIM);
        mma_pv<<<grid, 256, PV_SMEM_BYTES>>>(ph, pl, vh, vl, out);
    }
}

// round 17
// speedup vs baseline: 1.2105x; 1.0174x over previous
#include <cuda_runtime.h>
#include <cuda_bf16.h>
#include <cstdint>
#include <math.h>

#define BDIM 4
#define TDIM 2048
#define CDIM 1024
#define HDIM 2048

#define BM 128
#define BN 128
#define BK 32
#define SPADH 40                 // bf16 per smem row (80B, LDSM conflict-free)
#define TILE_E (BM * SPADH)
#define TILE_B (TILE_E * 2)
#define SMEM_BYTES (2 * 4 * TILE_B)   // 81920 -> 2 CTAs/SM

// PV kernel: B staged row-major [k][n], 32 x 136 bf16
#define SPADB 136
#define PV_A_E (BM * SPADH)
#define PV_B_E (BK * SPADB)
#define PV_STAGE_E (2 * PV_A_E + 2 * PV_B_E)
#define PV_SMEM_BYTES (2 * PV_STAGE_E * 2)     // 75776

// ---- global scratch planes (allocation-free rule) ----
#define NXC ((size_t)BDIM * TDIM * CDIM)
#define NWH ((size_t)HDIM * CDIM)
#define NTH ((size_t)BDIM * TDIM * HDIM)
#define NTT ((size_t)BDIM * TDIM * TDIM)
__device__ __nv_bfloat16 g_xh[NXC], g_xl[NXC];
__device__ __nv_bfloat16 g_wh[3][NWH], g_wl[3][NWH];
__device__ __nv_bfloat16 g_qkvh[3 * NTH], g_qkvl[3 * NTH];
__device__ float g_s[NTT];
__device__ __nv_bfloat16 g_ph[NTT], g_pl[NTT];

__device__ __forceinline__ void mma_bf16(float* c, const uint32_t* a, const uint32_t* b) {
    asm volatile(
        "mma.sync.aligned.m16n8k16.row.col.f32.bf16.bf16.f32 "
        "{%0,%1,%2,%3}, {%4,%5,%6,%7}, {%8,%9}, {%0,%1,%2,%3};"
        : "+f"(c[0]), "+f"(c[1]), "+f"(c[2]), "+f"(c[3])
        : "r"(a[0]), "r"(a[1]), "r"(a[2]), "r"(a[3]), "r"(b[0]), "r"(b[1]));
}

__device__ __forceinline__ void ldsm_x4(uint32_t* r, uint32_t addr) {
    asm volatile("ldmatrix.sync.aligned.m8n8.x4.shared.b16 {%0,%1,%2,%3}, [%4];"
                 : "=r"(r[0]), "=r"(r[1]), "=r"(r[2]), "=r"(r[3]) : "r"(addr));
}

__device__ __forceinline__ void ldsm_x4_t(uint32_t* r, uint32_t addr) {
    asm volatile("ldmatrix.sync.aligned.m8n8.x4.trans.shared.b16 {%0,%1,%2,%3}, [%4];"
                 : "=r"(r[0]), "=r"(r[1]), "=r"(r[2]), "=r"(r[3]) : "r"(addr));
}

#define CP_COMMIT() asm volatile("cp.async.commit_group;" ::: "memory")
#define CP_WAIT0()  asm volatile("cp.async.wait_group 0;" ::: "memory")

// ---------------- 3xBF16 NT GEMM ----------------
// tri=0: m0=by*BM, n0=bx*BN (dense). tri=1: bx is a linear lower-triangle index
// over (i,j) tile pairs, m0=i*BM, n0=j*BN (causal QK^T, no dead CTAs).
__global__ __launch_bounds__(256, 2) void mma_nt(
    const __nv_bfloat16* __restrict__ Ah, const __nv_bfloat16* __restrict__ Al,
    const __nv_bfloat16* __restrict__ Bh, const __nv_bfloat16* __restrict__ Bl,
    float* __restrict__ Cf, __nv_bfloat16* __restrict__ Ch, __nv_bfloat16* __restrict__ Cl,
    int K, int ldc, long sA, long sB, long sC, int tri, int split)
{
    int m0, n0;
    if (tri) {
        int t = blockIdx.x;
        int i = (int)((sqrtf(8.0f * t + 1.0f) - 1.0f) * 0.5f);
        while ((i + 1) * (i + 2) / 2 <= t) i++;
        while (i * (i + 1) / 2 > t) i--;
        int j = t - i * (i + 1) / 2;
        m0 = i * BM;  n0 = j * BN;
    } else {
        m0 = blockIdx.y * BM;  n0 = blockIdx.x * BN;
    }

    const int b = blockIdx.z;
    Ah += (long)b * sA;  Al += (long)b * sA;
    Bh += (long)b * sB;  Bl += (long)b * sB;

    extern __shared__ __nv_bfloat16 sm[];
    const uint32_t smb = (uint32_t)__cvta_generic_to_shared(sm);

    const int tid  = threadIdx.x;
    const int wid  = tid >> 5;
    const int lane = tid & 31;
    const int g  = lane >> 2;
    const int tg = lane & 3;
    const int wm = (wid >> 2) * 64;
    const int wn = (wid & 3) * 32;

    const uint32_t a_base = smb + (uint32_t)(((wm + (lane & 15)) * SPADH + ((lane >> 4) << 3)) * 2);
    const uint32_t b_base = smb + (uint32_t)(((wn + ((lane >> 4) << 3) + (lane & 7)) * SPADH
                                              + (((lane >> 3) & 1) << 3)) * 2);

    const int nstages = K / BK;

    const int r0c = tid >> 2,          c0c = tid & 3;
    const int r1c = (tid + 256) >> 2,  c1c = (tid + 256) & 3;

    const __nv_bfloat16* planes[4] = {Ah, Al, Bh, Bl};
    const int rbase[4] = {m0, m0, n0, n0};

    auto load_stage = [&](int buf, int k0) {
        #pragma unroll
        for (int p = 0; p < 4; p++) {
            __nv_bfloat16* tb = sm + (buf * 4 + p) * TILE_E;
            {
                uint32_t dst = (uint32_t)__cvta_generic_to_shared(tb + r0c * SPADH + c0c * 8);
                const void* src = planes[p] + (long)(rbase[p] + r0c) * K + k0 + c0c * 8;
                asm volatile("cp.async.cg.shared.global [%0], [%1], 16;" :: "r"(dst), "l"(src));
            }
            {
                uint32_t dst = (uint32_t)__cvta_generic_to_shared(tb + r1c * SPADH + c1c * 8);
                const void* src = planes[p] + (long)(rbase[p] + r1c) * K + k0 + c1c * 8;
                asm volatile("cp.async.cg.shared.global [%0], [%1], 16;" :: "r"(dst), "l"(src));
            }
        }
        CP_COMMIT();
    };

    float acc[4][4][4] = {};

    load_stage(0, 0);

    for (int s = 0; s < nstages; s++) {
        CP_WAIT0();
        __syncthreads();
        if (s + 1 < nstages) load_stage((s + 1) & 1, (s + 1) * BK);

        const uint32_t tAh = (uint32_t)(((s & 1) * 4 + 0) * TILE_B);
        const uint32_t tAl = (uint32_t)(((s & 1) * 4 + 1) * TILE_B);
        const uint32_t tBh = (uint32_t)(((s & 1) * 4 + 2) * TILE_B);
        const uint32_t tBl = (uint32_t)(((s & 1) * 4 + 3) * TILE_B);

        #pragma unroll
        for (int ks = 0; ks < BK; ks += 16) {
            const uint32_t ksb = (uint32_t)(ks * 2);
            uint32_t af[4][4], bh[2][4];

            #pragma unroll
            for (int mt = 0; mt < 4; mt++)
                ldsm_x4(af[mt], a_base + tAh + (uint32_t)(mt * 16 * SPADH * 2) + ksb);
            #pragma unroll
            for (int p = 0; p < 2; p++)
                ldsm_x4(bh[p], b_base + tBh + (uint32_t)(p * 16 * SPADH * 2) + ksb);
            #pragma unroll
            for (int mt = 0; mt < 4; mt++)
                #pragma unroll
                for (int nt = 0; nt < 4; nt++)
                    mma_bf16(acc[mt][nt], af[mt], &bh[nt >> 1][(nt & 1) * 2]);

            uint32_t bl[2][4];
            #pragma unroll
            for (int p = 0; p < 2; p++)
                ldsm_x4(bl[p], b_base + tBl + (uint32_t)(p * 16 * SPADH * 2) + ksb);
            #pragma unroll
            for (int mt = 0; mt < 4; mt++)
                #pragma unroll
                for (int nt = 0; nt < 4; nt++)
                    mma_bf16(acc[mt][nt], af[mt], &bl[nt >> 1][(nt & 1) * 2]);

            #pragma unroll
            for (int mt = 0; mt < 4; mt++)
                ldsm_x4(af[mt], a_base + tAl + (uint32_t)(mt * 16 * SPADH * 2) + ksb);
            #pragma unroll
            for (int mt = 0; mt < 4; mt++)
                #pragma unroll
                for (int nt = 0; nt < 4; nt++)
                    mma_bf16(acc[mt][nt], af[mt], &bh[nt >> 1][(nt & 1) * 2]);
        }
    }

    if (split) {
        Ch += (long)blockIdx.z * sC;  Cl += (long)blockIdx.z * sC;
        #pragma unroll
        for (int mt = 0; mt < 4; mt++) {
            #pragma unroll
            for (int nt = 0; nt < 4; nt++) {
                const int row = m0 + wm + mt * 16 + g;
                const int col = n0 + wn + nt * 8 + tg * 2;
                #pragma unroll
                for (int h = 0; h < 2; h++) {
                    float2 v = {acc[mt][nt][2 * h], acc[mt][nt][2 * h + 1]};
                    __nv_bfloat162 hp = __float22bfloat162_rn(v);
                    __nv_bfloat162 lp = __float22bfloat162_rn(make_float2(
                        v.x - __bfloat162float(hp.x), v.y - __bfloat162float(hp.y)));
                    long off = (long)(row + 8 * h) * ldc + col;
                    *(__nv_bfloat162*)&Ch[off] = hp;
                    *(__nv_bfloat162*)&Cl[off] = lp;
                }
            }
        }
    } else {
        Cf += (long)blockIdx.z * sC;
        #pragma unroll
        for (int mt = 0; mt < 4; mt++) {
            #pragma unroll
            for (int nt = 0; nt < 4; nt++) {
                const int row = m0 + wm + mt * 16 + g;
                const int col = n0 + wn + nt * 8 + tg * 2;
                float2 lo = {acc[mt][nt][0], acc[mt][nt][1]};
                float2 hi = {acc[mt][nt][2], acc[mt][nt][3]};
                *(float2*)&Cf[(long)row * ldc + col] = lo;
                *(float2*)&Cf[(long)(row + 8) * ldc + col] = hi;
            }
        }
    }
}

// ---------------- PV GEMM (heavy tiles first) ----------------
__global__ __launch_bounds__(256, 2) void mma_pv(
    const __nv_bfloat16* __restrict__ Ph, const __nv_bfloat16* __restrict__ Pl,
    const __nv_bfloat16* __restrict__ Vh, const __nv_bfloat16* __restrict__ Vl,
    float* __restrict__ O)
{
    const int m_idx = (int)(gridDim.y - 1 - blockIdx.y);   // heavy (large m0) first
    const int m0 = m_idx * BM;
    const int n0 = blockIdx.x * BN;
    const int b = blockIdx.z;
    Ph += (long)b * TDIM * TDIM;  Pl += (long)b * TDIM * TDIM;
    Vh += (long)b * TDIM * HDIM;  Vl += (long)b * TDIM * HDIM;
    O  += (long)b * TDIM * HDIM;

    extern __shared__ __nv_bfloat16 sm[];
    const uint32_t smb = (uint32_t)__cvta_generic_to_shared(sm);

    const int tid  = threadIdx.x;
    const int wid  = tid >> 5;
    const int lane = tid & 31;
    const int g  = lane >> 2;
    const int tg = lane & 3;
    const int wm = (wid >> 2) * 64;
    const int wn = (wid & 3) * 32;

    const uint32_t a_base = smb + (uint32_t)(((wm + (lane & 15)) * SPADH + ((lane >> 4) << 3)) * 2);
    const uint32_t b_base = smb + (uint32_t)(((((lane >> 3) & 1) * 8 + (lane & 7)) * SPADB
                                              + wn + ((lane >> 4) << 3)) * 2);

    const int kEnd = m0 + BM;
    const int nstages = kEnd / BK;

    const int r0c = tid >> 2,          c0c = tid & 3;
    const int r1c = (tid + 256) >> 2,  c1c = (tid + 256) & 3;
    const int br0 = tid >> 4,          bc0 = tid & 15;
    const int br1 = (tid + 256) >> 4,  bc1 = (tid + 256) & 15;

    auto load_stage = [&](int buf, int k0) {
        const uint32_t sb = (uint32_t)(buf * PV_STAGE_E);
        const __nv_bfloat16* aps[2] = {Ph, Pl};
        #pragma unroll
        for (int p = 0; p < 2; p++) {
            uint32_t tb = sb + (uint32_t)(p * PV_A_E);
            {
                uint32_t dst = smb + (tb + (uint32_t)(r0c * SPADH + c0c * 8)) * 2;
                const void* src = aps[p] + (long)(m0 + r0c) * TDIM + k0 + c0c * 8;
                asm volatile("cp.async.cg.shared.global [%0], [%1], 16;" :: "r"(dst), "l"(src));
            }
            {
                uint32_t dst = smb + (tb + (uint32_t)(r1c * SPADH + c1c * 8)) * 2;
                const void* src = aps[p] + (long)(m0 + r1c) * TDIM + k0 + c1c * 8;
                asm volatile("cp.async.cg.shared.global [%0], [%1], 16;" :: "r"(dst), "l"(src));
            }
        }
        const __nv_bfloat16* bps[2] = {Vh, Vl};
        #pragma unroll
        for (int p = 0; p < 2; p++) {
            uint32_t tb = sb + (uint32_t)(2 * PV_A_E + p * PV_B_E);
            {
                uint32_t dst = smb + (tb + (uint32_t)(br0 * SPADB + bc0 * 8)) * 2;
                const void* src = bps[p] + (long)(k0 + br0) * HDIM + n0 + bc0 * 8;
                asm volatile("cp.async.cg.shared.global [%0], [%1], 16;" :: "r"(dst), "l"(src));
            }
            {
                uint32_t dst = smb + (tb + (uint32_t)(br1 * SPADB + bc1 * 8)) * 2;
                const void* src = bps[p] + (long)(k0 + br1) * HDIM + n0 + bc1 * 8;
                asm volatile("cp.async.cg.shared.global [%0], [%1], 16;" :: "r"(dst), "l"(src));
            }
        }
        CP_COMMIT();
    };

    float acc[4][4][4] = {};

    load_stage(0, 0);

    for (int s = 0; s < nstages; s++) {
        CP_WAIT0();
        __syncthreads();
        if (s + 1 < nstages) load_stage((s + 1) & 1, (s + 1) * BK);

        const uint32_t sb  = (uint32_t)((s & 1) * PV_STAGE_E * 2);
        const uint32_t tAh = sb;
        const uint32_t tAl = sb + (uint32_t)(PV_A_E * 2);
        const uint32_t tBh = sb + (uint32_t)(2 * PV_A_E * 2);
        const uint32_t tBl = sb + (uint32_t)((2 * PV_A_E + PV_B_E) * 2);

        #pragma unroll
        for (int ks = 0; ks < BK; ks += 16) {
            const uint32_t ksa = (uint32_t)(ks * 2);
            const uint32_t ksb = (uint32_t)(ks * SPADB * 2);
            uint32_t af[4][4], bh[2][4];

            #pragma unroll
            for (int mt = 0; mt < 4; mt++)
                ldsm_x4(af[mt], a_base + tAh + (uint32_t)(mt * 16 * SPADH * 2) + ksa);
            #pragma unroll
            for (int p = 0; p < 2; p++)
                ldsm_x4_t(bh[p], b_base + tBh + (uint32_t)(p * 16 * 2) + ksb);
            #pragma unroll
            for (int mt = 0; mt < 4; mt++)
                #pragma unroll
                for (int nt = 0; nt < 4; nt++)
                    mma_bf16(acc[mt][nt], af[mt], &bh[nt >> 1][(nt & 1) * 2]);

            uint32_t bl[2][4];
            #pragma unroll
            for (int p = 0; p < 2; p++)
                ldsm_x4_t(bl[p], b_base + tBl + (uint32_t)(p * 16 * 2) + ksb);
            #pragma unroll
            for (int mt = 0; mt < 4; mt++)
                #pragma unroll
                for (int nt = 0; nt < 4; nt++)
                    mma_bf16(acc[mt][nt], af[mt], &bl[nt >> 1][(nt & 1) * 2]);

            #pragma unroll
            for (int mt = 0; mt < 4; mt++)
                ldsm_x4(af[mt], a_base + tAl + (uint32_t)(mt * 16 * SPADH * 2) + ksa);
            #pragma unroll
            for (int mt = 0; mt < 4; mt++)
                #pragma unroll
                for (int nt = 0; nt < 4; nt++)
                    mma_bf16(acc[mt][nt], af[mt], &bh[nt >> 1][(nt & 1) * 2]);
        }
    }

    #pragma unroll
    for (int mt = 0; mt < 4; mt++) {
        #pragma unroll
        for (int nt = 0; nt < 4; nt++) {
            const int row = m0 + wm + mt * 16 + g;
            const int col = n0 + wn + nt * 8 + tg * 2;
            float2 lo = {acc[mt][nt][0], acc[mt][nt][1]};
            float2 hi = {acc[mt][nt][2], acc[mt][nt][3]};
            *(float2*)&O[(long)row * HDIM + col] = lo;
            *(float2*)&O[(long)(row + 8) * HDIM + col] = hi;
        }
    }
}

// ---------------- f32 -> hi/lo bf16 planes ----------------
__global__ __launch_bounds__(256) void split_f32(
    const float* __restrict__ src, __nv_bfloat16* __restrict__ h,
    __nv_bfloat16* __restrict__ l, long n4)
{
    long i = ((long)blockIdx.x * 256 + threadIdx.x);
    if (i >= n4) return;
    float4 v = *(const float4*)(src + i * 4);
    __nv_bfloat162 h01 = __float22bfloat162_rn(make_float2(v.x, v.y));
    __nv_bfloat162 h23 = __float22bfloat162_rn(make_float2(v.z, v.w));
    __nv_bfloat162 l01 = __float22bfloat162_rn(make_float2(
        v.x - __bfloat162float(h01.x), v.y - __bfloat162float(h01.y)));
    __nv_bfloat162 l23 = __float22bfloat162_rn(make_float2(
        v.z - __bfloat162float(h23.x), v.w - __bfloat162float(h23.y)));
    *(__nv_bfloat162*)&h[i * 4]     = h01;
    *(__nv_bfloat162*)&h[i * 4 + 2] = h23;
    *(__nv_bfloat162*)&l[i * 4]     = l01;
    *(__nv_bfloat162*)&l[i * 4 + 2] = l23;
}

__global__ __launch_bounds__(256) void split_w3(
    const float* __restrict__ W0, const float* __restrict__ W1, const float* __restrict__ W2,
    __nv_bfloat16* __restrict__ h, __nv_bfloat16* __restrict__ l, long n4)
{
    const float* srcs[3] = {W0, W1, W2};
    const float* src = srcs[blockIdx.y];
    h += (long)blockIdx.y * NWH;
    l += (long)blockIdx.y * NWH;
    long i = ((long)blockIdx.x * 256 + threadIdx.x);
    if (i >= n4) return;
    float4 v = *(const float4*)(src + i * 4);
    __nv_bfloat162 h01 = __float22bfloat162_rn(make_float2(v.x, v.y));
    __nv_bfloat162 h23 = __float22bfloat162_rn(make_float2(v.z, v.w));
    __nv_bfloat162 l01 = __float22bfloat162_rn(make_float2(
        v.x - __bfloat162float(h01.x), v.y - __bfloat162float(h01.y)));
    __nv_bfloat162 l23 = __float22bfloat162_rn(make_float2(
        v.z - __bfloat162float(h23.x), v.w - __bfloat162float(h23.y)));
    *(__nv_bfloat162*)&h[i * 4]     = h01;
    *(__nv_bfloat162*)&h[i * 4 + 2] = h23;
    *(__nv_bfloat162*)&l[i * 4]     = l01;
    *(__nv_bfloat162*)&l[i * 4 + 2] = l23;
}

// ---------------- causal softmax -> hi/lo bf16 P planes ----------------
__global__ __launch_bounds__(256) void softmax_causal(
    const float* __restrict__ S, __nv_bfloat16* __restrict__ Ph,
    __nv_bfloat16* __restrict__ Pl, float scale)
{
    const int t = blockIdx.x;
    const int b = blockIdx.y;
    const long ro = ((long)b * TDIM + t) * TDIM;
    const float* row = S + ro;
    const int n = t + 1;
    const int nend = ((t >> 7) + 1) << 7;
    const int tid = threadIdx.x;

    __shared__ float red[256];

    float mx = -INFINITY;
    for (int i = tid; i < n; i += 256) mx = fmaxf(mx, row[i] * scale);
    red[tid] = mx;
    __syncthreads();
    for (int s = 128; s > 0; s >>= 1) {
        if (tid < s) red[tid] = fmaxf(red[tid], red[tid + s]);
        __syncthreads();
    }
    mx = red[0];
    __syncthreads();

    float sum = 0.f;
    for (int i = tid; i < n; i += 256) sum += __expf(row[i] * scale - mx);
    red[tid] = sum;
    __syncthreads();
    for (int s = 128; s > 0; s >>= 1) {
        if (tid < s) red[tid] += red[tid + s];
        __syncthreads();
    }
    const float inv = 1.0f / red[0];

    for (int i = tid; i < n; i += 256) {
        float p = __expf(row[i] * scale - mx) * inv;
        __nv_bfloat16 hp = __float2bfloat16_rn(p);
        Ph[ro + i] = hp;
        Pl[ro + i] = __float2bfloat16_rn(p - __bfloat162float(hp));
    }
    const __nv_bfloat16 z = __float2bfloat16_rn(0.f);
    for (int i = n + tid; i < nend; i += 256) { Ph[ro + i] = z; Pl[ro + i] = z; }
}

// ---------------- driver ----------------
extern "C" void kernel_launch(void* const* d_in, const int* in_sizes, int n_in,
                              void* d_out, int out_size)
{
    const float* x  = (const float*)d_in[0];
    const float* Wk = (const float*)d_in[1];
    const float* Wq = (const float*)d_in[2];
    const float* Wv = (const float*)d_in[3];
    float* out = (float*)d_out;

    __nv_bfloat16 *xh, *xl, *wh0, *wl0, *qkvh, *qkvl, *ph, *pl;
    float* s;
    cudaGetSymbolAddress((void**)&xh,   g_xh);    cudaGetSymbolAddress((void**)&xl,   g_xl);
    cudaGetSymbolAddress((void**)&wh0,  g_wh);    cudaGetSymbolAddress((void**)&wl0,  g_wl);
    cudaGetSymbolAddress((void**)&qkvh, g_qkvh);  cudaGetSymbolAddress((void**)&qkvl, g_qkvl);
    cudaGetSymbolAddress((void**)&ph,   g_ph);    cudaGetSymbolAddress((void**)&pl,   g_pl);
    cudaGetSymbolAddress((void**)&s,    g_s);

    cudaFuncSetAttribute(mma_nt, cudaFuncAttributeMaxDynamicSharedMemorySize, SMEM_BYTES);
    cudaFuncSetAttribute(mma_pv, cudaFuncAttributeMaxDynamicSharedMemorySize, PV_SMEM_BYTES);

    const int M = BDIM * TDIM;   // 8192
    const int NT = TDIM / BM;    // 16 tiles per side
    const int NTRI = NT * (NT + 1) / 2;   // 136

    // split inputs into hi/lo bf16 planes (weight order: q, k, v)
    {
        long nx4 = NXC / 4, nw4 = NWH / 4;
        split_f32<<<(unsigned)((nx4 + 255) / 256), 256>>>(x, xh, xl, nx4);
        dim3 gw((unsigned)((nw4 + 255) / 256), 3);
        split_w3<<<gw, 256>>>(Wq, Wk, Wv, wh0, wl0, nw4);
    }

    // All three projections in ONE launch
    {
        dim3 grid(HDIM / BN, M / BM, 3);
        mma_nt<<<grid, 256, SMEM_BYTES>>>(xh, xl, wh0, wl0,
                                          nullptr, qkvh, qkvl, CDIM, HDIM,
                                          0, (long)NWH, (long)NTH, 0, 1);
    }

    const __nv_bfloat16 *qh = qkvh,           *ql = qkvl;
    const __nv_bfloat16 *kh = qkvh + NTH,     *kl = qkvl + NTH;
    const __nv_bfloat16 *vh = qkvh + 2 * NTH, *vl = qkvl + 2 * NTH;

    // S = Q K^T: compact lower-triangle grid (no dead CTAs)
    {
        dim3 grid(NTRI, 1, BDIM);
        mma_nt<<<grid, 256, SMEM_BYTES>>>(qh, ql, kh, kl, s, nullptr, nullptr,
                                          HDIM, TDIM, (long)TDIM * HDIM, (long)TDIM * HDIM,
                                          (long)TDIM * TDIM, 1, 0);
    }

    // softmax -> P planes
    {
        dim3 grid(TDIM, BDIM);
        softmax_causal<<<grid, 256>>>(s, ph, pl, 1.0f / sqrtf((float)HDIM));
    }

    // O = P V, heavy m-tiles scheduled first
    {
        dim3 grid(HDIM / BN, TDIM / BM, BDIM);
        mma_pv<<<grid, 256, PV_SMEM_BYTES>>>(ph, pl, vh, vl, out);
    }
}